// round 3
// baseline (speedup 1.0000x reference)
#include <cuda_runtime.h>
#include <math.h>

#define BATCH 128
#define TT 512
#define NN 512
#define NCTA 128          // 4 batch-groups x 32 n-groups
#define NTHREADS 256
#define TB 32             // batch rows per CTA
#define TN 16             // n columns per CTA
#define SROW 516          // padded smem row stride (floats) -> bank-conflict-free

// ---------------- persistent device state (no allocs allowed) ----------------
__device__ float g_Wi[NN][NN];          // repacked Wi[:,1:]
__device__ float g_Wh[NN][NN];          // repacked Wh[:,1:]
__device__ float g_w0[NN];              // Wi[:,0] + Wh[:,0]
__device__ float g_bs[NN];              // bi + bh
__device__ float g_wfk[NN];             // Wf[0,1:]
__device__ float g_hbuf[2][BATCH][NN];
__device__ float g_cbuf[2][BATCH][NN];  // c BEFORE the deferred f*B rank-1 update
__device__ float g_fbuf[3][BATCH];      // rotating f accumulators
__device__ unsigned g_count = 0;
__device__ unsigned g_exit  = 0;
__device__ volatile unsigned g_sense = 0;

// Sense-style global barrier with monotone per-launch targets.
__device__ __forceinline__ void grid_barrier(unsigned target) {
    __syncthreads();
    if (threadIdx.x == 0) {
        __threadfence();                       // publish my writes
        unsigned old = atomicAdd(&g_count, 1u);
        if (old == (unsigned)gridDim.x - 1u) {
            atomicExch(&g_count, 0u);
            __threadfence();
            g_sense = target;                  // release
        } else {
            while (g_sense < target) { }       // volatile spin (L2)
            __threadfence();                   // acquire
        }
    }
    __syncthreads();
}

__global__ void __launch_bounds__(NTHREADS, 1)
hippo_kernel(const float* __restrict__ x,   const float* __restrict__ h0,
             const float* __restrict__ c0,  const float* __restrict__ Wi,
             const float* __restrict__ bi,  const float* __restrict__ Wh,
             const float* __restrict__ bh,  const float* __restrict__ Wf,
             const float* __restrict__ bf,  const float* __restrict__ A_stack,
             const float* __restrict__ B_stack, float* __restrict__ out)
{
    extern __shared__ float sm[];
    float* c_s = sm;                 // [TB][SROW]  c_eff (c + f_prev*B_prev)
    float* h_s = sm + TB * SROW;     // [TB][SROW]

    const int cta   = blockIdx.x;
    const int bgrp  = cta >> 5;          // 0..3
    const int ngrp  = cta & 31;          // 0..31
    const int bbase = bgrp * TB;
    const int nbase = ngrp * TN;
    const int tid   = threadIdx.x;

    const float wf0 = Wf[0];
    const float bfv = bf[0];

    // ----------------------------- init phase -------------------------------
    {
        // repack weights: 4 rows per CTA, drop the x-column, align rows
        const int r0 = cta * 4;
        for (int i = tid; i < 4 * NN; i += NTHREADS) {
            int nr = r0 + (i >> 9);
            int k  = i & (NN - 1);
            g_Wi[nr][k] = Wi[nr * (NN + 1) + 1 + k];
            g_Wh[nr][k] = Wh[nr * (NN + 1) + 1 + k];
        }
        if (tid < 4) {
            int nr = r0 + tid;
            g_w0[nr]  = Wi[nr * (NN + 1)] + Wh[nr * (NN + 1)];
            g_bs[nr]  = bi[nr] + bh[nr];
            g_wfk[nr] = Wf[1 + nr];
        }
        // state init: CTA r owns batch row r
        const int b = cta;
        for (int k = tid; k < NN; k += NTHREADS) {
            g_hbuf[0][b][k] = h0[b * NN + k];
            g_cbuf[0][b][k] = c0[b * NN + k];
        }
        if (tid == 0) {
            g_fbuf[0][b] = 0.f;                              // f_{-1} = 0
            g_fbuf[1][b] = wf0 * x[b * TT + 0] + bfv;        // seed for f_0
        }
    }
    grid_barrier(1u);

    // per-thread tile: 2 batch rows x 1 column
    const int n_loc = tid & (TN - 1);
    const int bp    = tid >> 4;            // 0..15
    const int n_g   = nbase + n_loc;
    const int bg0   = bbase + bp;
    const int bg1   = bbase + bp + 16;

    int fcur = 0, fnxt = 1, fzero = 2;     // == t%3, (t+1)%3, (t+2)%3

    for (int t = 0; t < TT; t++) {
        const int cur = t & 1, nxt = cur ^ 1;

        // ---- stage c_eff = c + f_prev*B_prev and h into shared memory ----
        const float* Bprev = B_stack + (size_t)(t ? (t - 1) : 0) * NN;
        for (int i = tid; i < TB * (NN / 4); i += NTHREADS) {
            int bl  = i >> 7;              // / 128
            int k4  = i & 127;
            int bgl = bbase + bl;
            float  fp = g_fbuf[fcur][bgl];
            float4 cv = ((const float4*)(&g_cbuf[cur][bgl][0]))[k4];
            float4 bv = ((const float4*)Bprev)[k4];
            cv.x += fp * bv.x; cv.y += fp * bv.y;
            cv.z += fp * bv.z; cv.w += fp * bv.w;
            ((float4*)(c_s + bl * SROW))[k4] = cv;
            ((float4*)(h_s + bl * SROW))[k4] =
                ((const float4*)(&g_hbuf[cur][bgl][0]))[k4];
        }
        __syncthreads();

        // ---- the three contractions over k (full fp32, float4 blocked) ----
        const float4* wiP = (const float4*)(&g_Wi[n_g][0]);
        const float4* whP = (const float4*)(&g_Wh[n_g][0]);
        const float4* aP  = (const float4*)(A_stack + ((size_t)t * NN + n_g) * NN);
        const float4* cA  = (const float4*)(c_s + bp * SROW);
        const float4* cB  = (const float4*)(c_s + (bp + 16) * SROW);
        const float4* hA  = (const float4*)(h_s + bp * SROW);
        const float4* hB  = (const float4*)(h_s + (bp + 16) * SROW);
        float ga0 = 0.f, ga1 = 0.f, ca0 = 0.f, ca1 = 0.f;
        #pragma unroll 4
        for (int k4 = 0; k4 < NN / 4; k4++) {
            float4 w1 = wiP[k4], w2 = whP[k4], av = aP[k4];
            float4 c1 = cA[k4],  c2 = cB[k4];
            float4 h1 = hA[k4],  h2 = hB[k4];
            ga0 += w1.x*c1.x + w1.y*c1.y + w1.z*c1.z + w1.w*c1.w;
            ga0 += w2.x*h1.x + w2.y*h1.y + w2.z*h1.z + w2.w*h1.w;
            ga1 += w1.x*c2.x + w1.y*c2.y + w1.z*c2.z + w1.w*c2.w;
            ga1 += w2.x*h2.x + w2.y*h2.y + w2.z*h2.z + w2.w*h2.w;
            ca0 += av.x*c1.x + av.y*c1.y + av.z*c1.z + av.w*c1.w;
            ca1 += av.x*c2.x + av.y*c2.y + av.z*c2.z + av.w*c2.w;
        }

        // ---- pointwise epilogue ----
        float xv0 = x[(size_t)bg0 * TT + t];
        float xv1 = x[(size_t)bg1 * TT + t];
        float w0n = g_w0[n_g], bsn = g_bs[n_g];
        float gt0 = ga0 + xv0 * w0n + bsn;
        float gt1 = ga1 + xv1 * w0n + bsn;
        float o0  = 1.f / (1.f + expf(-gt0));
        float o1  = 1.f / (1.f + expf(-gt1));
        float hn0 = o0 * tanhf(c_s[bp * SROW + n_g]);
        float hn1 = o1 * tanhf(c_s[(bp + 16) * SROW + n_g]);

        g_hbuf[nxt][bg0][n_g] = hn0;
        g_hbuf[nxt][bg1][n_g] = hn1;
        g_cbuf[nxt][bg0][n_g] = ca0;      // f_t*B_t added lazily next step
        g_cbuf[nxt][bg1][n_g] = ca1;
        out[((size_t)bg0 * TT + t) * NN + n_g] = hn0;
        out[((size_t)bg1 * TT + t) * NN + n_g] = hn1;

        // ---- f_t partial: reduce the CTA's 16 columns, one atomic per (CTA,b)
        float v0 = g_wfk[n_g] * hn0;
        float v1 = g_wfk[n_g] * hn1;
        #pragma unroll
        for (int off = 8; off > 0; off >>= 1) {
            v0 += __shfl_down_sync(0xffffffffu, v0, off, TN);
            v1 += __shfl_down_sync(0xffffffffu, v1, off, TN);
        }
        if (n_loc == 0) {
            atomicAdd(&g_fbuf[fnxt][bg0], v0);
            atomicAdd(&g_fbuf[fnxt][bg1], v1);
        }

        // ---- seed f accumulator for step t+1 (buffer (t+2)%3, safe now) ----
        if (ngrp == 0 && tid < TB) {
            int bgl = bbase + tid;
            float seed = 0.f;
            if (t + 1 < TT) seed = wf0 * x[(size_t)bgl * TT + (t + 1)] + bfv;
            g_fbuf[fzero][bgl] = seed;
        }

        grid_barrier((unsigned)(t + 2));

        int tmp = fcur; fcur = fnxt; fnxt = fzero; fzero = tmp;
    }

    // ---- final c_T = c_tmp + f_{T-1} * B_{T-1}  (barrier above guarantees f)
    {
        const int cur = TT & 1;                       // buffer written at t=511
        const float* Blast = B_stack + (size_t)(TT - 1) * NN;
        float ff0 = g_fbuf[fcur][bg0];                // fcur == T%3 after loop
        float ff1 = g_fbuf[fcur][bg1];
        float cf0 = g_cbuf[cur][bg0][n_g] + ff0 * Blast[n_g];
        float cf1 = g_cbuf[cur][bg1][n_g] + ff1 * Blast[n_g];
        size_t base = (size_t)BATCH * TT * NN;
        out[base + (size_t)bg0 * NN + n_g] = cf0;
        out[base + (size_t)bg1 * NN + n_g] = cf1;
    }

    // ---- reset barrier state so graph replays start clean ----
    __syncthreads();
    if (tid == 0) {
        unsigned old = atomicAdd(&g_exit, 1u);
        if (old == (unsigned)NCTA - 1u) {   // everyone passed their last spin
            atomicExch(&g_exit, 0u);
            atomicExch(&g_count, 0u);
            __threadfence();
            g_sense = 0;
        }
    }
}

extern "C" void kernel_launch(void* const* d_in, const int* in_sizes, int n_in,
                              void* d_out, int out_size) {
    (void)in_sizes; (void)n_in; (void)out_size;
    const float* x   = (const float*)d_in[0];
    const float* h0  = (const float*)d_in[1];
    const float* c0  = (const float*)d_in[2];
    const float* Wi  = (const float*)d_in[3];
    const float* bi  = (const float*)d_in[4];
    const float* Wh  = (const float*)d_in[5];
    const float* bh  = (const float*)d_in[6];
    const float* Wf  = (const float*)d_in[7];
    const float* bf  = (const float*)d_in[8];
    const float* A_s = (const float*)d_in[9];
    const float* B_s = (const float*)d_in[10];
    float* out = (float*)d_out;

    const int smem_bytes = 2 * TB * SROW * (int)sizeof(float);   // 132096
    cudaFuncSetAttribute(hippo_kernel,
                         cudaFuncAttributeMaxDynamicSharedMemorySize, smem_bytes);
    hippo_kernel<<<NCTA, NTHREADS, smem_bytes>>>(x, h0, c0, Wi, bi, Wh, bh,
                                                 Wf, bf, A_s, B_s, out);
}

// round 5
// speedup vs baseline: 4.1092x; 4.1092x over previous
#include <cuda_runtime.h>
#include <math.h>

#define BATCH 128
#define TT 512
#define NN 512
#define NCTA 128          // 4 batch-groups x 32 n-groups
#define NTHREADS 256
#define TB 32             // batch rows per CTA
#define TN 16             // n columns per CTA

// shared memory layout (float offsets)
#define OFF_WI 0          // [16][512] swizzled
#define OFF_WH 8192       // [16][512] swizzled
#define OFF_A  16384      // [16][512] swizzled
#define OFF_C  24576      // [32][512]
#define OFF_H  40960      // [32][512]
#define SMEM_FLOATS 57344 // 229376 bytes

// ---------------- persistent device state (no allocs allowed) ----------------
__device__ float g_hbuf[2][BATCH][NN];
__device__ float g_cbuf[2][BATCH][NN];  // c BEFORE the deferred f*B rank-1 update
__device__ float g_fbuf[3][BATCH];      // rotating f accumulators
__device__ unsigned g_count = 0;
__device__ unsigned g_exit  = 0;
__device__ volatile unsigned g_sense = 0;

// Sense-style global barrier with monotone per-launch targets.
__device__ __forceinline__ void grid_barrier(unsigned target) {
    __syncthreads();
    if (threadIdx.x == 0) {
        __threadfence();                       // publish my writes
        unsigned old = atomicAdd(&g_count, 1u);
        if (old == (unsigned)gridDim.x - 1u) {
            atomicExch(&g_count, 0u);
            __threadfence();
            g_sense = target;                  // release
        } else {
            while (g_sense < target) { }       // volatile spin (L2)
            __threadfence();                   // acquire
        }
    }
    __syncthreads();
}

__global__ void __launch_bounds__(NTHREADS, 1)
hippo_kernel(const float* __restrict__ x,   const float* __restrict__ h0,
             const float* __restrict__ c0,  const float* __restrict__ Wi,
             const float* __restrict__ bi,  const float* __restrict__ Wh,
             const float* __restrict__ bh,  const float* __restrict__ Wf,
             const float* __restrict__ bf,  const float* __restrict__ A_stack,
             const float* __restrict__ B_stack, float* __restrict__ out)
{
    extern __shared__ float sm[];

    const int cta   = blockIdx.x;
    const int bgrp  = cta >> 5;          // 0..3
    const int ngrp  = cta & 31;          // 0..31
    const int bbase = bgrp * TB;
    const int nbase = ngrp * TN;
    const int tid   = threadIdx.x;

    const float wf0 = Wf[0];
    const float bfv = bf[0];

    // per-thread tile: 2 batch rows x 1 column
    const int n_loc = tid & (TN - 1);
    const int bp    = tid >> 4;            // 0..15
    const int n_g   = nbase + n_loc;
    const int bg0   = bbase + bp;
    const int bg1   = bbase + bp + 16;

    // per-thread scalar params (loaded once, straight from inputs)
    const float w0n  = Wi[(size_t)n_g * (NN + 1)] + Wh[(size_t)n_g * (NN + 1)];
    const float bsn  = bi[n_g] + bh[n_g];
    const float wfkn = Wf[1 + n_g];

    // ----------------------------- init phase -------------------------------
    // Stage Wi/Wh slices (rows nbase..nbase+15, x-column dropped) into smem,
    // swizzled: logical float4 k4 of row r lives at phys f4 index (k4 ^ (r&7)).
    for (int j = tid; j < TN * NN; j += NTHREADS) {
        int r = j >> 9;           // 0..15
        int k = j & (NN - 1);
        int f4  = (k >> 2) ^ (r & 7);
        int pos = r * NN + f4 * 4 + (k & 3);
        sm[OFF_WI + pos] = Wi[(size_t)(nbase + r) * (NN + 1) + 1 + k];
        sm[OFF_WH + pos] = Wh[(size_t)(nbase + r) * (NN + 1) + 1 + k];
    }

    // Prologue: prefetch A[0] tile (16 rows x 512) into registers, coalesced.
    float4 aPre[8];
    {
        const float4* Ab = (const float4*)A_stack + (size_t)nbase * (NN / 4);
        #pragma unroll
        for (int r = 0; r < 8; r++) aPre[r] = Ab[tid + NTHREADS * r];
    }

    // state init: CTA r owns batch row r
    {
        const int b = cta;
        for (int k = tid; k < NN; k += NTHREADS) {
            g_hbuf[0][b][k] = h0[b * NN + k];
            g_cbuf[0][b][k] = c0[b * NN + k];
        }
        if (tid == 0) {
            g_fbuf[0][b] = 0.f;                              // f_{-1} = 0
            g_fbuf[1][b] = wf0 * x[(size_t)b * TT + 0] + bfv; // seed for f_0
        }
    }
    grid_barrier(1u);

    int fcur = 0, fnxt = 1, fzero = 2;     // == t%3, (t+1)%3, (t+2)%3

    for (int t = 0; t < TT; t++) {
        const int cur = t & 1, nxt = cur ^ 1;

        // ---- store prefetched A[t] into smem (swizzled) ----
        #pragma unroll
        for (int r = 0; r < 8; r++) {
            int j   = tid + NTHREADS * r;
            int row = j >> 7, k4 = j & 127;
            ((float4*)(sm + OFF_A))[row * 128 + (k4 ^ (row & 7))] = aPre[r];
        }

        // ---- stage c_eff = c + f_prev*B_prev and h into shared memory ----
        const float* Bprev = B_stack + (size_t)(t ? (t - 1) : 0) * NN;
        for (int i = tid; i < TB * (NN / 4); i += NTHREADS) {  // 16 iters
            int bl  = i >> 7;
            int k4  = i & 127;
            int bgl = bbase + bl;
            float  fp = g_fbuf[fcur][bgl];
            float4 cv = ((const float4*)(&g_cbuf[cur][bgl][0]))[k4];
            float4 bv = ((const float4*)Bprev)[k4];
            cv.x += fp * bv.x; cv.y += fp * bv.y;
            cv.z += fp * bv.z; cv.w += fp * bv.w;
            ((float4*)(sm + OFF_C + bl * NN))[k4] = cv;
            ((float4*)(sm + OFF_H + bl * NN))[k4] =
                ((const float4*)(&g_hbuf[cur][bgl][0]))[k4];
        }
        __syncthreads();

        // ---- issue prefetch of A[t+1] (consumed next step; hides DRAM) ----
        {
            int t1 = (t + 1 < TT) ? (t + 1) : (TT - 1);
            const float4* Ab = (const float4*)A_stack
                             + ((size_t)t1 * NN + nbase) * (NN / 4);
            #pragma unroll
            for (int r = 0; r < 8; r++) aPre[r] = Ab[tid + NTHREADS * r];
        }

        // ---- three contractions over k: all operands in smem ----
        const int sr = n_loc & 7;
        const float4* wiR = (const float4*)(sm + OFF_WI) + n_loc * 128;
        const float4* whR = (const float4*)(sm + OFF_WH) + n_loc * 128;
        const float4* aR  = (const float4*)(sm + OFF_A)  + n_loc * 128;
        const float4* cA  = (const float4*)(sm + OFF_C + bp * NN);
        const float4* cB  = (const float4*)(sm + OFF_C + (bp + 16) * NN);
        const float4* hA  = (const float4*)(sm + OFF_H + bp * NN);
        const float4* hB  = (const float4*)(sm + OFF_H + (bp + 16) * NN);
        float ga0 = 0.f, ga1 = 0.f, ca0 = 0.f, ca1 = 0.f;
        #pragma unroll 4
        for (int k4 = 0; k4 < NN / 4; k4++) {
            int kp = k4 ^ sr;                  // swizzled slot for logical k4
            float4 w1 = wiR[kp], w2 = whR[kp], av = aR[kp];
            float4 c1 = cA[k4],  c2 = cB[k4];
            float4 h1 = hA[k4],  h2 = hB[k4];
            ga0 += w1.x*c1.x + w1.y*c1.y + w1.z*c1.z + w1.w*c1.w;
            ga0 += w2.x*h1.x + w2.y*h1.y + w2.z*h1.z + w2.w*h1.w;
            ga1 += w1.x*c2.x + w1.y*c2.y + w1.z*c2.z + w1.w*c2.w;
            ga1 += w2.x*h2.x + w2.y*h2.y + w2.z*h2.z + w2.w*h2.w;
            ca0 += av.x*c1.x + av.y*c1.y + av.z*c1.z + av.w*c1.w;
            ca1 += av.x*c2.x + av.y*c2.y + av.z*c2.z + av.w*c2.w;
        }

        // ---- pointwise epilogue ----
        float xv0 = x[(size_t)bg0 * TT + t];
        float xv1 = x[(size_t)bg1 * TT + t];
        float gt0 = ga0 + xv0 * w0n + bsn;
        float gt1 = ga1 + xv1 * w0n + bsn;
        float o0  = 1.f / (1.f + expf(-gt0));
        float o1  = 1.f / (1.f + expf(-gt1));
        float hn0 = o0 * tanhf(sm[OFF_C + bp * NN + n_g]);
        float hn1 = o1 * tanhf(sm[OFF_C + (bp + 16) * NN + n_g]);

        g_hbuf[nxt][bg0][n_g] = hn0;
        g_hbuf[nxt][bg1][n_g] = hn1;
        g_cbuf[nxt][bg0][n_g] = ca0;      // f_t*B_t added lazily next step
        g_cbuf[nxt][bg1][n_g] = ca1;
        out[((size_t)bg0 * TT + t) * NN + n_g] = hn0;
        out[((size_t)bg1 * TT + t) * NN + n_g] = hn1;

        // ---- f_t partial: reduce the CTA's 16 columns, one atomic per (CTA,b)
        float v0 = wfkn * hn0;
        float v1 = wfkn * hn1;
        #pragma unroll
        for (int off = 8; off > 0; off >>= 1) {
            v0 += __shfl_down_sync(0xffffffffu, v0, off, TN);
            v1 += __shfl_down_sync(0xffffffffu, v1, off, TN);
        }
        if (n_loc == 0) {
            atomicAdd(&g_fbuf[fnxt][bg0], v0);
            atomicAdd(&g_fbuf[fnxt][bg1], v1);
        }

        // ---- seed f accumulator for step t+1 (buffer (t+2)%3, safe now) ----
        if (ngrp == 0 && tid < TB) {
            int bgl = bbase + tid;
            float seed = 0.f;
            if (t + 1 < TT) seed = wf0 * x[(size_t)bgl * TT + (t + 1)] + bfv;
            g_fbuf[fzero][bgl] = seed;
        }

        grid_barrier((unsigned)(t + 2));

        int tmp = fcur; fcur = fnxt; fnxt = fzero; fzero = tmp;
    }

    // ---- final c_T = c_tmp + f_{T-1} * B_{T-1}  (barrier above guarantees f)
    {
        const int cur = TT & 1;                       // buffer written at t=511
        const float* Blast = B_stack + (size_t)(TT - 1) * NN;
        float ff0 = g_fbuf[fcur][bg0];
        float ff1 = g_fbuf[fcur][bg1];
        float cf0 = g_cbuf[cur][bg0][n_g] + ff0 * Blast[n_g];
        float cf1 = g_cbuf[cur][bg1][n_g] + ff1 * Blast[n_g];
        size_t base = (size_t)BATCH * TT * NN;
        out[base + (size_t)bg0 * NN + n_g] = cf0;
        out[base + (size_t)bg1 * NN + n_g] = cf1;
    }

    // ---- reset barrier state so graph replays start clean ----
    __syncthreads();
    if (tid == 0) {
        unsigned old = atomicAdd(&g_exit, 1u);
        if (old == (unsigned)NCTA - 1u) {
            atomicExch(&g_exit, 0u);
            atomicExch(&g_count, 0u);
            __threadfence();
            g_sense = 0;
        }
    }
}

extern "C" void kernel_launch(void* const* d_in, const int* in_sizes, int n_in,
                              void* d_out, int out_size) {
    (void)in_sizes; (void)n_in; (void)out_size;
    const float* x   = (const float*)d_in[0];
    const float* h0  = (const float*)d_in[1];
    const float* c0  = (const float*)d_in[2];
    const float* Wi  = (const float*)d_in[3];
    const float* bi  = (const float*)d_in[4];
    const float* Wh  = (const float*)d_in[5];
    const float* bh  = (const float*)d_in[6];
    const float* Wf  = (const float*)d_in[7];
    const float* bf  = (const float*)d_in[8];
    const float* A_s = (const float*)d_in[9];
    const float* B_s = (const float*)d_in[10];
    float* out = (float*)d_out;

    const int smem_bytes = SMEM_FLOATS * (int)sizeof(float);   // 229376
    cudaFuncSetAttribute(hippo_kernel,
                         cudaFuncAttributeMaxDynamicSharedMemorySize, smem_bytes);
    hippo_kernel<<<NCTA, NTHREADS, smem_bytes>>>(x, h0, c0, Wi, bi, Wh, bh,
                                                 Wf, bf, A_s, B_s, out);
}